// round 2
// baseline (speedup 1.0000x reference)
#include <cuda_runtime.h>
#include <cstdint>

// WeightedBCELoss: out[b,s] = (labels[b,s]==0) ? -log(1-pred) : -weight[b]*log(pred)
// pred [4096,8192] f32, labels [4096,8192] i32, weight [4096] f32.
// HBM-streaming: ~402 MiB traffic. R2: non-temporal ld/st + 2x float4 per
// thread (deeper MLP), flat index with row = idx>>11 (SENT/4 = 2048).

#define BATCH 4096
#define SENT  8192
#define V4_PER_ROW (SENT / 4)          // 2048 = 2^11
#define ROW_SHIFT 11

__global__ __launch_bounds__(256, 8)
void wbce_kernel(const float4* __restrict__ pred,
                 const int4*   __restrict__ labels,
                 const float*  __restrict__ weight,
                 float4*       __restrict__ out)
{
    // Each block covers 512 consecutive float4s; each thread does 2 (stride 256).
    const long base = (long)blockIdx.x * 512 + threadIdx.x;
    const long i0 = base;
    const long i1 = base + 256;

    // Front-batched loads: 4 independent 16B loads -> MLP=4 per thread.
    float4 p0 = __ldcs(&pred[i0]);
    float4 p1 = __ldcs(&pred[i1]);
    int4   l0 = __ldcs(&labels[i0]);
    int4   l1 = __ldcs(&labels[i1]);

    const int r0 = (int)(i0 >> ROW_SHIFT);
    const int r1 = (int)(i1 >> ROW_SHIFT);
    const float w0 = __ldg(&weight[r0]);
    const float w1 = __ldg(&weight[r1]);

    float4 o0, o1;
    {
        float a, s;
        a = (l0.x == 0) ? (1.0f - p0.x) : p0.x;  s = (l0.x == 0) ? 1.0f : w0;
        o0.x = -s * __logf(a);
        a = (l0.y == 0) ? (1.0f - p0.y) : p0.y;  s = (l0.y == 0) ? 1.0f : w0;
        o0.y = -s * __logf(a);
        a = (l0.z == 0) ? (1.0f - p0.z) : p0.z;  s = (l0.z == 0) ? 1.0f : w0;
        o0.z = -s * __logf(a);
        a = (l0.w == 0) ? (1.0f - p0.w) : p0.w;  s = (l0.w == 0) ? 1.0f : w0;
        o0.w = -s * __logf(a);

        a = (l1.x == 0) ? (1.0f - p1.x) : p1.x;  s = (l1.x == 0) ? 1.0f : w1;
        o1.x = -s * __logf(a);
        a = (l1.y == 0) ? (1.0f - p1.y) : p1.y;  s = (l1.y == 0) ? 1.0f : w1;
        o1.y = -s * __logf(a);
        a = (l1.z == 0) ? (1.0f - p1.z) : p1.z;  s = (l1.z == 0) ? 1.0f : w1;
        o1.z = -s * __logf(a);
        a = (l1.w == 0) ? (1.0f - p1.w) : p1.w;  s = (l1.w == 0) ? 1.0f : w1;
        o1.w = -s * __logf(a);
    }

    __stcs(&out[i0], o0);
    __stcs(&out[i1], o1);
}

extern "C" void kernel_launch(void* const* d_in, const int* in_sizes, int n_in,
                              void* d_out, int out_size)
{
    const float4* pred   = (const float4*)d_in[0];
    const int4*   labels = (const int4*)d_in[1];
    const float*  weight = (const float*)d_in[2];
    float4*       out    = (float4*)d_out;

    // total float4 = 4096*8192/4 = 8,388,608 ; 512 per block -> 16384 blocks
    const int total_v4 = BATCH * V4_PER_ROW;
    dim3 block(256);
    dim3 grid(total_v4 / 512);
    wbce_kernel<<<grid, block>>>(pred, labels, weight, out);
}